// round 10
// baseline (speedup 1.0000x reference)
#include <cuda_runtime.h>

// SymmetryControl (square-symmetry branch), B=16,C=96,H=96,W=96.
// Butterfly-orbit kernel, 8-blocks/SM variant:
//   orbit pair (p, 5-p) of a row sits on adjacent lanes (even/odd); each
//   thread holds ONE orbit (4 f4 of p=x*w + 4 f4 of w) and pulls the partner
//   orbit via shfl.bfly(xor=1). __launch_bounds__(128,8) caps regs at 64.
//
// Output elem i = 4t+c:
//   shifts: f4 (t+18)%24, (t+12)%24, (t+6)%24, component c
//   flips:  f4 (5-t)%24 (partner slot (4-m)&3) and (11-t)%24 (slot (1-m)&3),
//           component 3-c (reversed)

#define W4 24
#define NT 128

__device__ __forceinline__ float4 shfl_bfly4(float4 v) {
    float4 r;
    r.x = __shfl_xor_sync(0xffffffffu, v.x, 1);
    r.y = __shfl_xor_sync(0xffffffffu, v.y, 1);
    r.z = __shfl_xor_sync(0xffffffffu, v.z, 1);
    r.w = __shfl_xor_sync(0xffffffffu, v.w, 1);
    return r;
}

__global__ __launch_bounds__(NT, 8)
void symmetry_control_bfly8(const float4* __restrict__ x4,
                            const float*  __restrict__ s,
                            const float4* __restrict__ w4,
                            float4* __restrict__ out4,
                            int rows_per_batch /* C*H = 9216 */)
{
    // lanes (2q, 2q+1) hold orbits (p, 5-p) of one row.
    const unsigned tid   = blockIdx.x * NT + threadIdx.x;
    const unsigned gpair = tid >> 1;
    const unsigned side  = tid & 1;
    const unsigned row   = gpair / 3;
    const unsigned p     = gpair % 3;
    const unsigned o     = side ? (5 - p) : p;      // my orbit id (0..5)
    const unsigned base  = row * W4 + o;            // fits 32-bit (max ~3.5M)

    // Gates (latency hidden under the bulk loads below).
    const unsigned b = row / (unsigned)rows_per_batch;
    const float g0 = 1.0f / (1.0f + __expf(-s[b * 5 + 0]));
    const float g1 = 1.0f / (1.0f + __expf(-s[b * 5 + 1]));
    const float g2 = 1.0f / (1.0f + __expf(-s[b * 5 + 2]));
    const float g3 = 1.0f / (1.0f + __expf(-s[b * 5 + 3]));
    const float g4 = 1.0f / (1.0f + __expf(-s[b * 5 + 4]));

    // My orbit: 8 independent streaming LDG.128.
    float4 P[4], W[4];
#pragma unroll
    for (int k = 0; k < 4; k++) {
        const float4 xv = __ldcs(&x4[base + 6 * k]);
        W[k] = __ldcs(&w4[base + 6 * k]);
        P[k] = make_float4(xv.x * W[k].x, xv.y * W[k].y,
                           xv.z * W[k].z, xv.w * W[k].w);
    }

#pragma unroll
    for (int m = 0; m < 4; m++) {
        const int m1 = (m + 1) & 3;      // +6  f4 (270deg)
        const int m2 = (m + 2) & 3;      // +12 f4 (180deg)
        const int m3 = (m + 3) & 3;      // +18 f4 (90deg)
        const int kf90  = (4 - m) & 3;   // flip90  slot in partner orbit
        const int kf180 = (1 - m) & 3;   // flip180 slot in partner orbit

        // Partner orbit's values for this m (components used reversed).
        const float4 qf = shfl_bfly4(P[kf90]);
        const float4 vf = shfl_bfly4(W[kf90]);
        const float4 qg = shfl_bfly4(P[kf180]);
        const float4 vg = shfl_bfly4(W[kf180]);

        const float4 p0 = P[m], pa = P[m3], pb = P[m2], pc = P[m1];
        const float4 w0 = W[m], wa = W[m3], wb = W[m2], wc = W[m1];

        float4 oo;
        {   float a = p0.x;
            a = fmaf(g0, pa.x, a); a = fmaf(g1, pb.x, a); a = fmaf(g2, pc.x, a);
            a = fmaf(g3, qf.w, a); a = fmaf(g4, qg.w, a);
            float d = w0.x;
            d = fmaf(g0, wa.x, d); d = fmaf(g1, wb.x, d); d = fmaf(g2, wc.x, d);
            d = fmaf(g3, vf.w, d); d = fmaf(g4, vg.w, d);
            oo.x = __fdividef(a, d); }
        {   float a = p0.y;
            a = fmaf(g0, pa.y, a); a = fmaf(g1, pb.y, a); a = fmaf(g2, pc.y, a);
            a = fmaf(g3, qf.z, a); a = fmaf(g4, qg.z, a);
            float d = w0.y;
            d = fmaf(g0, wa.y, d); d = fmaf(g1, wb.y, d); d = fmaf(g2, wc.y, d);
            d = fmaf(g3, vf.z, d); d = fmaf(g4, vg.z, d);
            oo.y = __fdividef(a, d); }
        {   float a = p0.z;
            a = fmaf(g0, pa.z, a); a = fmaf(g1, pb.z, a); a = fmaf(g2, pc.z, a);
            a = fmaf(g3, qf.y, a); a = fmaf(g4, qg.y, a);
            float d = w0.z;
            d = fmaf(g0, wa.z, d); d = fmaf(g1, wb.z, d); d = fmaf(g2, wc.z, d);
            d = fmaf(g3, vf.y, d); d = fmaf(g4, vg.y, d);
            oo.z = __fdividef(a, d); }
        {   float a = p0.w;
            a = fmaf(g0, pa.w, a); a = fmaf(g1, pb.w, a); a = fmaf(g2, pc.w, a);
            a = fmaf(g3, qf.x, a); a = fmaf(g4, qg.x, a);
            float d = w0.w;
            d = fmaf(g0, wa.w, d); d = fmaf(g1, wb.w, d); d = fmaf(g2, wc.w, d);
            d = fmaf(g3, vf.x, d); d = fmaf(g4, vg.x, d);
            oo.w = __fdividef(a, d); }

        __stcs(&out4[base + 6 * m], oo);
    }
}

extern "C" void kernel_launch(void* const* d_in, const int* in_sizes, int n_in,
                              void* d_out, int out_size)
{
    const float4* x4 = (const float4*)d_in[0];
    const float*  s  = (const float*)d_in[1];
    const float4* w4 = (const float4*)d_in[2];
    float4* out4 = (float4*)d_out;

    const long long total = in_sizes[0];          // B*C*H*W = 14,155,776
    const int B = in_sizes[1] / 5;                // 16
    const long long rows = total / 96;            // 147,456
    const int rows_per_batch = (int)(rows / B);   // 9216

    const long long nthreads = rows * 6;          // 884,736
    const long long nblocks  = nthreads / NT;     // 6912 (exact)
    symmetry_control_bfly8<<<(unsigned)nblocks, NT>>>(x4, s, w4, out4, rows_per_batch);
}

// round 11
// speedup vs baseline: 1.0943x; 1.0943x over previous
#include <cuda_runtime.h>

// SymmetryControl (square-symmetry branch), B=16,C=96,H=96,W=96.
// Butterfly-orbit kernel (R9 dataflow) + packed f32x2 math:
//   - orbit pair (p, 5-p) of a row on adjacent lanes; each thread holds ONE
//     orbit (4 f4 of p=x*w + 4 f4 of w, stored as packed f32x2 halves) and
//     pulls partner-orbit values via shfl.bfly(xor=1), packed REVERSED at
//     shuffle time (flip operands are component-reversed).
//   - numerator/denominator chains run on fma.rn.f32x2 (half the FMA issue).
//   - rolling flip-operand window: per-m flip180 slot == previous m's flip90
//     slot, so only one new shuffled operand set per m after the first.
// Output elem i = 4t+c:
//   shifts: f4 (t+18)%24, (t+12)%24, (t+6)%24, component c
//   flips:  f4 (5-t)%24 (partner slot (4-m)&3) and (11-t)%24 (slot (1-m)&3),
//           component 3-c (reversed)

#define W4 24
#define NT 128

typedef unsigned long long ull;

__device__ __forceinline__ ull pk2(float lo, float hi) {
    ull r; asm("mov.b64 %0, {%1, %2};" : "=l"(r) : "f"(lo), "f"(hi)); return r;
}
__device__ __forceinline__ void upk2(float& lo, float& hi, ull v) {
    asm("mov.b64 {%0, %1}, %2;" : "=f"(lo), "=f"(hi) : "l"(v));
}
__device__ __forceinline__ ull fma2(ull a, ull b, ull c) {
    ull d; asm("fma.rn.f32x2 %0, %1, %2, %3;" : "=l"(d) : "l"(a), "l"(b), "l"(c));
    return d;
}
__device__ __forceinline__ ull mul2(ull a, ull b) {
    ull d; asm("mul.rn.f32x2 %0, %1, %2;" : "=l"(d) : "l"(a), "l"(b));
    return d;
}
// Shuffle a packed pair from lane^1 and return it with halves SWAPPED
// (builds the component-reversed flip operand directly).
__device__ __forceinline__ ull shfl_rev(ull v) {
    float lo, hi; upk2(lo, hi, v);
    const float a = __shfl_xor_sync(0xffffffffu, hi, 1);
    const float b = __shfl_xor_sync(0xffffffffu, lo, 1);
    return pk2(a, b);
}

__global__ __launch_bounds__(NT, 7)
void symmetry_control_bfly2(const float4* __restrict__ x4,
                            const float*  __restrict__ s,
                            const float4* __restrict__ w4,
                            float4* __restrict__ out4,
                            int rows_per_batch /* C*H = 9216 */)
{
    // lanes (2q, 2q+1) hold orbits (p, 5-p) of one row.
    const unsigned tid   = blockIdx.x * NT + threadIdx.x;
    const unsigned gpair = tid >> 1;
    const unsigned side  = tid & 1;
    const unsigned row   = gpair / 3;
    const unsigned p     = gpair % 3;
    const unsigned o     = side ? (5 - p) : p;   // my orbit id (0..5)
    const unsigned base  = row * W4 + o;         // fits 32-bit

    // Gates, packed (g,g). Latency hidden under bulk loads.
    const unsigned b = row / (unsigned)rows_per_batch;
    const float g0 = 1.0f / (1.0f + __expf(-s[b * 5 + 0]));
    const float g1 = 1.0f / (1.0f + __expf(-s[b * 5 + 1]));
    const float g2 = 1.0f / (1.0f + __expf(-s[b * 5 + 2]));
    const float g3 = 1.0f / (1.0f + __expf(-s[b * 5 + 3]));
    const float g4 = 1.0f / (1.0f + __expf(-s[b * 5 + 4]));
    const ull G0 = pk2(g0, g0), G1 = pk2(g1, g1), G2 = pk2(g2, g2),
              G3 = pk2(g3, g3), G4 = pk2(g4, g4);

    // My orbit: 8 independent streaming LDG.128; keep as packed halves.
    ull Pl[4], Ph[4], Wl[4], Wh[4];   // (x,y) and (z,w) of p=x*w and w
#pragma unroll
    for (int k = 0; k < 4; k++) {
        const float4 xv = __ldcs(&x4[base + 6 * k]);
        const float4 wv = __ldcs(&w4[base + 6 * k]);
        Wl[k] = pk2(wv.x, wv.y);
        Wh[k] = pk2(wv.z, wv.w);
        Pl[k] = mul2(pk2(xv.x, xv.y), Wl[k]);
        Ph[k] = mul2(pk2(xv.z, xv.w), Wh[k]);
    }

    // Rolling flip-operand window. For output components (0,1) the flip
    // operand is reversed (z,w)-half of the partner slot; for (2,3) it is
    // the reversed (x,y)-half.
    ull qaL, qaH, vaL, vaH;   // flip90 operands (slot (4-m)&3)
    ull qbL, qbH, vbL, vbH;   // flip180 operands (slot (1-m)&3)

#pragma unroll
    for (int m = 0; m < 4; m++) {
        const int m1 = (m + 1) & 3;      // +6  f4 (270deg, gate g2)
        const int m2 = (m + 2) & 3;      // +12 f4 (180deg, gate g1)
        const int m3 = (m + 3) & 3;      // +18 f4 (90deg,  gate g0)
        const int kf90 = (4 - m) & 3;    // flip90 slot in partner orbit

        if (m == 0) {
            qaL = shfl_rev(Ph[0]); qaH = shfl_rev(Pl[0]);
            vaL = shfl_rev(Wh[0]); vaH = shfl_rev(Wl[0]);
            qbL = shfl_rev(Ph[1]); qbH = shfl_rev(Pl[1]);
            vbL = shfl_rev(Wh[1]); vbH = shfl_rev(Wl[1]);
        } else {
            // this m's flip180 slot == previous m's flip90 slot
            qbL = qaL; qbH = qaH; vbL = vaL; vbH = vaH;
            qaL = shfl_rev(Ph[kf90]); qaH = shfl_rev(Pl[kf90]);
            vaL = shfl_rev(Wh[kf90]); vaH = shfl_rev(Wl[kf90]);
        }

        // numerator halves (same op order as the proven scalar kernel)
        ull nL = Pl[m];
        nL = fma2(G0, Pl[m3], nL); nL = fma2(G1, Pl[m2], nL);
        nL = fma2(G2, Pl[m1], nL);
        nL = fma2(G3, qaL, nL);    nL = fma2(G4, qbL, nL);
        ull nH = Ph[m];
        nH = fma2(G0, Ph[m3], nH); nH = fma2(G1, Ph[m2], nH);
        nH = fma2(G2, Ph[m1], nH);
        nH = fma2(G3, qaH, nH);    nH = fma2(G4, qbH, nH);

        // denominator halves
        ull dL = Wl[m];
        dL = fma2(G0, Wl[m3], dL); dL = fma2(G1, Wl[m2], dL);
        dL = fma2(G2, Wl[m1], dL);
        dL = fma2(G3, vaL, dL);    dL = fma2(G4, vbL, dL);
        ull dH = Wh[m];
        dH = fma2(G0, Wh[m3], dH); dH = fma2(G1, Wh[m2], dH);
        dH = fma2(G2, Wh[m1], dH);
        dH = fma2(G3, vaH, dH);    dH = fma2(G4, vbH, dH);

        float n0, n1, n2, n3, d0, d1, d2, d3;
        upk2(n0, n1, nL); upk2(n2, n3, nH);
        upk2(d0, d1, dL); upk2(d2, d3, dH);

        float4 oo;
        oo.x = __fdividef(n0, d0);
        oo.y = __fdividef(n1, d1);
        oo.z = __fdividef(n2, d2);
        oo.w = __fdividef(n3, d3);

        __stcs(&out4[base + 6 * m], oo);
    }
}

extern "C" void kernel_launch(void* const* d_in, const int* in_sizes, int n_in,
                              void* d_out, int out_size)
{
    const float4* x4 = (const float4*)d_in[0];
    const float*  s  = (const float*)d_in[1];
    const float4* w4 = (const float4*)d_in[2];
    float4* out4 = (float4*)d_out;

    const long long total = in_sizes[0];          // B*C*H*W = 14,155,776
    const int B = in_sizes[1] / 5;                // 16
    const long long rows = total / 96;            // 147,456
    const int rows_per_batch = (int)(rows / B);   // 9216

    const long long nthreads = rows * 6;          // 884,736
    const long long nblocks  = nthreads / NT;     // 6912 (exact)
    symmetry_control_bfly2<<<(unsigned)nblocks, NT>>>(x4, s, w4, out4, rows_per_batch);
}